// round 14
// baseline (speedup 1.0000x reference)
#include <cuda_runtime.h>

#define XS 8192

// Scratch (allocation-free): Tpart [k][Bg][pq][s32][o32]
__device__ float g_Tpart[16 * 8 * 2 * 1024];

__device__ __forceinline__ float4 shfl_xor_f4(float4 v, int d) {
    float4 r;
    r.x = __shfl_xor_sync(0xffffffffu, v.x, d);
    r.y = __shfl_xor_sync(0xffffffffu, v.y, d);
    r.z = __shfl_xor_sync(0xffffffffu, v.z, d);
    r.w = __shfl_xor_sync(0xffffffffu, v.w, d);
    return r;
}

// ============================================================================
// K1: Tpart producer. grid = (k16, Bg8, shB4) = 512 blocks x 256 threads.
// Block: samples 8*shB..8*shB+7, B's 4*Bg..4*Bg+3 (m-pairs 2Bg, 2Bg+1).
// ============================================================================
__global__ void __launch_bounds__(256, 3) k1_tpart(
    const float* __restrict__ x,
    const float* __restrict__ w_off,
    const int*   __restrict__ perm)
{
    __shared__ float4 Wp4[544], Wm4[544];   // 32 rows x 17 f4  [o][m*8+iq]
    __shared__ float4 Sp4[136], Sm4[136];   // 8 rows x 17 f4   [s][m*8+iq]

    const int b = blockIdx.x, t = threadIdx.x;
    const int k = b >> 5, Bg = (b >> 2) & 7, shB = b & 3;

    // ---- W slice prefetch (f4 = B quad = two m-pairs) ----
    const float4* woff4 = (const float4*)w_off;   // [c][k][B/4]
    float4 wreg[4];
#pragma unroll
    for (int j = 0; j < 4; j++)
        wreg[j] = __ldg(&woff4[(j * 256 + t) * 128 + k * 8 + Bg]);

    // ---- gather 8 samples x 4 B x 8 rows; S± pooling ----
    {
        const int s = t >> 5, Bl = (t >> 3) & 3, iq = t & 7;
        const float4* x4 = (const float4*)x;
        float4 a = make_float4(0.f, 0.f, 0.f, 0.f);
        const int pbase = 32 * Bg + 8 * Bl;
        const int xbase = (8 * shB + s) * 2048;
#pragma unroll
        for (int r = 0; r < 8; r++) {
            int n = __ldg(&perm[pbase + r]);
            float4 v = __ldg(&x4[xbase + n * 8 + iq]);
            a.x += v.x; a.y += v.y; a.z += v.z; a.w += v.w;
        }
        float4 o4 = shfl_xor_f4(a, 8);            // partner Bl^1
        const int mloc = Bl >> 1;
        if ((Bl & 1) == 0) {                      // Sp = S_even + S_odd
            float4 p;
            p.x = a.x + o4.x; p.y = a.y + o4.y; p.z = a.z + o4.z; p.w = a.w + o4.w;
            Sp4[s * 17 + mloc * 8 + iq] = p;
        } else {                                  // Sm = S_even − S_odd = o4 − a
            float4 q;
            q.x = o4.x - a.x; q.y = o4.y - a.y; q.z = o4.z - a.z; q.w = o4.w - a.w;
            Sm4[s * 17 + mloc * 8 + iq] = q;
        }
    }

    // ---- W± -> smem ----
    {
        float* Wpf = (float*)Wp4;   // row o: 68 floats, [m*32 + i]
        float* Wmf = (float*)Wm4;
#pragma unroll
        for (int j = 0; j < 4; j++) {
            int c = j * 256 + t, o = c >> 5, i = c & 31;
            float4 w = wreg[j];
            Wpf[o * 68 +      i] = w.x + w.y;     // m0
            Wpf[o * 68 + 32 + i] = w.z + w.w;     // m1
            Wmf[o * 68 +      i] = w.x - w.y;
            Wmf[o * 68 + 32 + i] = w.z - w.w;
        }
    }
    __syncthreads();

    // ---- contraction (t < 128): tile 4s x 4o, K = 2m x 2j x f4 ----
    if (t < 128) {
        const int pq = t >> 6, sh = (t >> 5) & 1, og = (t >> 2) & 7, ih = t & 3;
        const float4* Wb = pq ? Wm4 : Wp4;
        const float4* Sb = pq ? Sm4 : Sp4;
        float acc[4][4];
#pragma unroll
        for (int j = 0; j < 16; j++) ((float*)acc)[j] = 0.f;
#pragma unroll
        for (int m = 0; m < 2; m++)
#pragma unroll
            for (int j = 0; j < 2; j++) {
                int iq = ih * 2 + j;
                float4 s4[4], w4[4];
#pragma unroll
                for (int ss = 0; ss < 4; ss++)
                    s4[ss] = Sb[(sh + 2 * ss) * 17 + m * 8 + iq];
#pragma unroll
                for (int oo = 0; oo < 4; oo++)
                    w4[oo] = Wb[(og + 8 * oo) * 17 + m * 8 + iq];
#pragma unroll
                for (int ss = 0; ss < 4; ss++)
#pragma unroll
                    for (int oo = 0; oo < 4; oo++)
                        acc[ss][oo] += w4[oo].x * s4[ss].x + w4[oo].y * s4[ss].y
                                     + w4[oo].z * s4[ss].z + w4[oo].w * s4[ss].w;
            }
        // ih reduce via warp butterfly (lane bits 0-1)
#pragma unroll
        for (int u = 0; u < 16; u++) {
            float v = ((float*)acc)[u];
            v += __shfl_xor_sync(0xffffffffu, v, 1);
            v += __shfl_xor_sync(0xffffffffu, v, 2);
            ((float*)acc)[u] = v;
        }
        float* Tdst = g_Tpart + ((k * 8 + Bg) * 2 + pq) * 1024;
#pragma unroll
        for (int ss = 0; ss < 4; ss++) {
            if (ih == ss) {
                int sglob = 8 * shB + sh + 2 * ss;
#pragma unroll
                for (int oo = 0; oo < 4; oo++)
                    Tdst[sglob * 32 + og + 8 * oo] = acc[ss][oo];
            }
        }
    }
}

// ============================================================================
// K2: finalize. grid = (k16, sp16) = 256 blocks x 256 threads.
// Block: output rows a = k*16..k*16+15 for samples {2sp, 2sp+1}.
// ============================================================================
__global__ void __launch_bounds__(256, 3) k2_final(
    const float* __restrict__ x,
    const float* __restrict__ w_diag,
    const float* __restrict__ b1,
    const int*   __restrict__ perm,
    float*       __restrict__ out)
{
    __shared__ float4 wdsh4[264];   // [iq*33 + o]
    __shared__ float4 tsh4[32];     // [p*16 + sL*8 + oq]
    __shared__ float  bsh[32];
    float* tshF = (float*)tsh4;

    const int b = blockIdx.x, t = threadIdx.x;
    const int k = b >> 4, sp = b & 15;
    const float4* x4 = (const float4*)x;

    if (t < 32) bsh[t] = __ldg(&b1[t]);

    const int sL = t >> 7, aa = (t >> 3) & 15, og = t & 7;
    const int n2 = __ldg(&perm[k * 16 + aa]);

    // x row prefetch
    float4 xr[8];
    {
        int base = (2 * sp + sL) * 2048 + n2 * 8;
#pragma unroll
        for (int iq = 0; iq < 8; iq++) xr[iq] = __ldg(&x4[base + iq]);
    }

    // T reduce (one warp, 16 f4 loads MLP) + Karatsuba combine via shfl
    if (t < 32) {
        const int p = t >> 4, sLr = (t >> 3) & 1, oq = t & 7;
        const float4* Tp4 = (const float4*)g_Tpart;
        float4 A = make_float4(0.f, 0.f, 0.f, 0.f);
#pragma unroll
        for (int Bg = 0; Bg < 8; Bg++) {
            float4 v = __ldcg(&Tp4[((k * 8 + Bg) * 2 + p) * 256
                                   + (2 * sp + sLr) * 8 + oq]);
            A.x += v.x; A.y += v.y; A.z += v.z; A.w += v.w;
        }
        float4 B = shfl_xor_f4(A, 16);   // partner parity
        const float c = 1.0f / 512.0f;
        float4 T;
        if (p == 0) {  // A=P, B=Q → T0=(P+Q)/512
            T.x = (A.x + B.x) * c; T.y = (A.y + B.y) * c;
            T.z = (A.z + B.z) * c; T.w = (A.w + B.w) * c;
        } else {       // A=Q, B=P → T1=(P−Q)/512
            T.x = (B.x - A.x) * c; T.y = (B.y - A.y) * c;
            T.z = (B.z - A.z) * c; T.w = (B.w - A.w) * c;
        }
        tsh4[p * 16 + sLr * 8 + oq] = T;
    }

    // w_diag column k -> smem [iq][o]
    {
        float* wdf = (float*)wdsh4;
#pragma unroll
        for (int j = 0; j < 4; j++) {
            int c = j * 256 + t, o = c >> 5, i = c & 31;
            wdf[((i >> 2) * 33 + o) * 4 + (i & 3)] = __ldg(&w_diag[c * 16 + k]);
        }
    }
    __syncthreads();

    // diag GEMM + T + bias, store
    float acc2[4];
#pragma unroll
    for (int oo = 0; oo < 4; oo++) acc2[oo] = bsh[og + 8 * oo];
#pragma unroll
    for (int iq = 0; iq < 8; iq++) {
        float4 xv = xr[iq];
#pragma unroll
        for (int oo = 0; oo < 4; oo++) {
            float4 wv = wdsh4[iq * 33 + og + 8 * oo];
            acc2[oo] += wv.x * xv.x + wv.y * xv.y + wv.z * xv.z + wv.w * xv.w;
        }
    }
    const int pa = aa >> 3;
    float* orow = out + (2 * sp + sL) * XS + n2 * 32;
#pragma unroll
    for (int oo = 0; oo < 4; oo++) {
        int o = og + 8 * oo;
        orow[o] = acc2[oo] + tshF[pa * 64 + sL * 32 + o];
    }
}

// ---------------------------------------------------------------------------
extern "C" void kernel_launch(void* const* d_in, const int* in_sizes, int n_in,
                              void* d_out, int out_size)
{
    const float* x      = (const float*)d_in[0];
    const float* w_diag = (const float*)d_in[1];
    const float* w_off  = (const float*)d_in[2];
    const float* b1     = (const float*)d_in[3];
    const int*   perm   = (const int*)d_in[4];
    float* out = (float*)d_out;

    k1_tpart<<<512, 256>>>(x, w_off, perm);
    k2_final<<<256, 256>>>(x, w_diag, b1, perm, out);
}

// round 17
// speedup vs baseline: 1.0019x; 1.0019x over previous
#include <cuda_runtime.h>

#define XS 8192

__device__ __forceinline__ float4 shfl_xor_add_f4(float4 v, int d) {
    float4 r;
    r.x = v.x + __shfl_xor_sync(0xffffffffu, v.x, d);
    r.y = v.y + __shfl_xor_sync(0xffffffffu, v.y, d);
    r.z = v.z + __shfl_xor_sync(0xffffffffu, v.z, d);
    r.w = v.w + __shfl_xor_sync(0xffffffffu, v.w, d);
    return r;
}

__global__ void __launch_bounds__(512, 1) __cluster_dims__(8, 1, 1)
fused_kernel(
    const float* __restrict__ x,
    const float* __restrict__ w_diag,
    const float* __restrict__ w_off,
    const float* __restrict__ b1,
    const int*   __restrict__ perm,
    float*       __restrict__ out)
{
    // f4 union: Wp[0,544) Wm[544,1088) Sp[1088,1632) Sm[1632,2176)
    __shared__ float4 SM4[2176];
    __shared__ float4 wdsh4[264];      // [iq*33 + o]
    __shared__ float4 Trcv4[512];      // 8192 B: [Bg][pq][sl][ogB] f4 — remote-filled
    __shared__ float  tshF[256];       // [pq][sl][o]
    __shared__ float  bsh[32];
    float* Trcv = (float*)Trcv4;

    const int b = blockIdx.x, t = threadIdx.x;
    const int k = b >> 3, sg = b & 7;  // cluster = 8 consecutive blocks, same k
    const float4* x4 = (const float4*)x;

    if (t < 32) bsh[t] = __ldg(&b1[t]);

    // ---- finalize-role indices + x row prefetch ----
    const int sL = t >> 7, aa = (t >> 3) & 15, og = t & 7;
    const int n2 = __ldg(&perm[k * 16 + aa]);
    float4 xr[8];
    {
        int base = (4 * sg + sL) * 2048 + n2 * 8;
#pragma unroll
        for (int iq = 0; iq < 8; iq++) xr[iq] = __ldg(&x4[base + iq]);
    }

    // ---- W prefetch ----
    const float4* woff4 = (const float4*)w_off;     // [c][k][B/4]
    float4 wreg[2];
#pragma unroll
    for (int j = 0; j < 2; j++)
        wreg[j] = __ldg(&woff4[(j * 512 + t) * 128 + k * 8 + sg]);

    // ---- w_diag column k -> smem [iq][o] ----
    {
        float* wdf = (float*)wdsh4;
#pragma unroll
        for (int j = 0; j < 2; j++) {
            int c = j * 512 + t;                    // c = o*32 + i
            int o = c >> 5, i = c & 31;
            wdf[((i >> 2) * 33 + o) * 4 + (i & 3)] = __ldg(&w_diag[c * 16 + k]);
        }
    }

    // ================= phase A: local gather + S± pooling ===================
    {
        const int sA = t >> 4, iqA = t & 7, rh = (t >> 3) & 1;
        float4 sB[4];
#pragma unroll
        for (int Bl = 0; Bl < 4; Bl++) {
            float4 a = make_float4(0.f, 0.f, 0.f, 0.f);
#pragma unroll
            for (int rr = 0; rr < 4; rr++) {
                int n = __ldg(&perm[sg * 32 + Bl * 8 + rh * 4 + rr]);
                float4 v = __ldg(&x4[sA * 2048 + n * 8 + iqA]);
                a.x += v.x; a.y += v.y; a.z += v.z; a.w += v.w;
            }
            sB[Bl] = a;
        }
#pragma unroll
        for (int Bl = 0; Bl < 4; Bl++) sB[Bl] = shfl_xor_add_f4(sB[Bl], 8);

        if (rh == 0) {   // Sp rows: [s*17 + m*8 + iq]
            float4 p0, p1;
            p0.x = sB[0].x + sB[1].x; p0.y = sB[0].y + sB[1].y;
            p0.z = sB[0].z + sB[1].z; p0.w = sB[0].w + sB[1].w;
            p1.x = sB[2].x + sB[3].x; p1.y = sB[2].y + sB[3].y;
            p1.z = sB[2].z + sB[3].z; p1.w = sB[2].w + sB[3].w;
            SM4[1088 + sA * 17 +     iqA] = p0;
            SM4[1088 + sA * 17 + 8 + iqA] = p1;
        } else {         // Sm rows
            float4 q0, q1;
            q0.x = sB[0].x - sB[1].x; q0.y = sB[0].y - sB[1].y;
            q0.z = sB[0].z - sB[1].z; q0.w = sB[0].w - sB[1].w;
            q1.x = sB[2].x - sB[3].x; q1.y = sB[2].y - sB[3].y;
            q1.z = sB[2].z - sB[3].z; q1.w = sB[2].w - sB[3].w;
            SM4[1632 + sA * 17 +     iqA] = q0;
            SM4[1632 + sA * 17 + 8 + iqA] = q1;
        }
    }

    // ---- W± -> smem ----
    {
        float* Wp = (float*)SM4;       // row o: 68 floats
        float* Wm = (float*)(SM4 + 544);
#pragma unroll
        for (int jj = 0; jj < 2; jj++) {
            int c = jj * 512 + t, o = c >> 5, i = c & 31;
            float4 w = wreg[jj];
            Wp[o * 68 +      i] = w.x + w.y;   // m=0
            Wp[o * 68 + 32 + i] = w.z + w.w;   // m=1
            Wm[o * 68 +      i] = w.x - w.y;
            Wm[o * 68 + 32 + i] = w.z - w.w;
        }
    }
    __syncthreads();

    // ================= phase B: contraction + DSMEM scatter ================
    {
        const int pq = t >> 8, sh = (t >> 5) & 7, ogB = (t >> 2) & 7, ih = t & 3;
        const float4* Wb = SM4 + (pq ? 544 : 0);
        const float4* Sb = SM4 + 1088 + (pq ? 544 : 0);
        float acc[4][4];
#pragma unroll
        for (int j = 0; j < 16; j++) ((float*)acc)[j] = 0.f;
#pragma unroll
        for (int m = 0; m < 2; m++)
#pragma unroll
            for (int j = 0; j < 2; j++) {
                int iq = ih * 2 + j;
                float4 s4[4], w4[4];
#pragma unroll
                for (int ss = 0; ss < 4; ss++)
                    s4[ss] = Sb[(sh + 8 * ss) * 17 + m * 8 + iq];
#pragma unroll
                for (int oo = 0; oo < 4; oo++)
                    w4[oo] = Wb[(ogB + 8 * oo) * 17 + m * 8 + iq];
#pragma unroll
                for (int ss = 0; ss < 4; ss++)
#pragma unroll
                    for (int oo = 0; oo < 4; oo++)
                        acc[ss][oo] += w4[oo].x * s4[ss].x + w4[oo].y * s4[ss].y
                                     + w4[oo].z * s4[ss].z + w4[oo].w * s4[ss].w;
            }
        // ih reduce via warp butterfly; lane ih keeps quarter ss==ih
#pragma unroll
        for (int u = 0; u < 16; u++) {
            float v = ((float*)acc)[u];
            v += __shfl_xor_sync(0xffffffffu, v, 1);
            v += __shfl_xor_sync(0xffffffffu, v, 2);
            ((float*)acc)[u] = v;
        }
        // owned sample s = sh + 8*ih → consumer rank cr = s>>2, slot sl = s&3
        const int s  = sh + 8 * ih;
        const int cr = s >> 2, sl = s & 3;
        float v0 = 0.f, v1 = 0.f, v2 = 0.f, v3 = 0.f;
#pragma unroll
        for (int ss = 0; ss < 4; ss++) {
            if (ih == ss) { v0 = acc[ss][0]; v1 = acc[ss][1]; v2 = acc[ss][2]; v3 = acc[ss][3]; }
        }
        // remote store: Trcv[myBg=sg][pq][sl][ogB] (byte strides 1024/512/128/16)
        unsigned int loc;
        asm("{ .reg .u64 a; cvta.to.shared.u64 a, %1; cvt.u32.u64 %0, a; }"
            : "=r"(loc) : "l"(Trcv4));
        loc += (unsigned int)(sg * 1024 + pq * 512 + sl * 128 + ogB * 16);
        unsigned int rem;
        asm("mapa.shared::cluster.u32 %0, %1, %2;" : "=r"(rem) : "r"(loc), "r"(cr));
        asm volatile("st.shared::cluster.v4.f32 [%0], {%1,%2,%3,%4};"
                     :: "r"(rem), "f"(v0), "f"(v1), "f"(v2), "f"(v3) : "memory");
    }

    // ---- cluster barrier (release our stores); diag GEMM in the gap --------
    asm volatile("barrier.cluster.arrive.aligned;" ::: "memory");

    float acc2[4];
#pragma unroll
    for (int oo = 0; oo < 4; oo++) acc2[oo] = bsh[og + 8 * oo];
#pragma unroll
    for (int iq = 0; iq < 8; iq++) {
        float4 xv = xr[iq];
#pragma unroll
        for (int oo = 0; oo < 4; oo++) {
            float4 wv = wdsh4[iq * 33 + og + 8 * oo];
            acc2[oo] += wv.x * xv.x + wv.y * xv.y + wv.z * xv.z + wv.w * xv.w;
        }
    }

    asm volatile("barrier.cluster.wait.aligned;" ::: "memory");

    // ---- reduce Trcv over Bg (pure LDS) -------------------------------------
    if (t < 256) {
        int pq2 = t >> 7, sl2 = (t >> 5) & 3, pos = t & 31;
        float v = 0.f;
#pragma unroll
        for (int b2 = 0; b2 < 8; b2++)
            v += Trcv[b2 * 256 + pq2 * 128 + sl2 * 32 + pos];
        int o = (pos >> 2) + 8 * (pos & 3);
        tshF[pq2 * 128 + sl2 * 32 + o] = v;
    }
    __syncthreads();

    // ---- combine T = (P±Q)/512, add, store ----------------------------------
    const int pa = aa >> 3;
    float* orow = out + (4 * sg + sL) * XS + n2 * 32;
#pragma unroll
    for (int oo = 0; oo < 4; oo++) {
        int o = og + 8 * oo;
        float P = tshF[      sL * 32 + o];
        float Q = tshF[128 + sL * 32 + o];
        float tv = (pa ? (P - Q) : (P + Q)) * (1.0f / 512.0f);
        orow[o] = acc2[oo] + tv;
    }
}

// ---------------------------------------------------------------------------
extern "C" void kernel_launch(void* const* d_in, const int* in_sizes, int n_in,
                              void* d_out, int out_size)
{
    const float* x      = (const float*)d_in[0];
    const float* w_diag = (const float*)d_in[1];
    const float* w_off  = (const float*)d_in[2];
    const float* b1     = (const float*)d_in[3];
    const int*   perm   = (const int*)d_in[4];
    float* out = (float*)d_out;

    fused_kernel<<<128, 512>>>(x, w_diag, w_off, b1, perm, out);
}